// round 13
// baseline (speedup 1.0000x reference)
#include <cuda_runtime.h>
#include <cuda_fp16.h>

#define NE 1200000
#define NN 50000
#define DF 64
#define HID 32

__device__ int g_idx_is64;

// fp16 per-node partials, one 128-byte line per node:
//   bytes [0,64)   : A'[n] = x[n]@W1[0:64] + b1   (32 fp16)
//   bytes [64,128) : B[n]  = x[n]@W1[64:128]      (32 fp16)
__device__ __align__(128) __half g_ABh[NN * 64];   // 6.4 MB (L2-resident)

// Hot weight matrix on the constant port.
__constant__ float cW2[HID * HID];      // 4 KB

// ---- packed f32x2 helpers (Blackwell sm_103a) ----
__device__ __forceinline__ unsigned long long pk2(float a, float b) {
    unsigned long long r;
    asm("mov.b64 %0, {%1, %2};" : "=l"(r) : "f"(a), "f"(b));
    return r;
}
__device__ __forceinline__ void upk2(unsigned long long v, float& a, float& b) {
    asm("mov.b64 {%0, %1}, %2;" : "=f"(a), "=f"(b) : "l"(v));
}
__device__ __forceinline__ unsigned long long fma2(unsigned long long a,
                                                   unsigned long long b,
                                                   unsigned long long c) {
    unsigned long long d;
    asm("fma.rn.f32x2 %0, %1, %2, %3;" : "=l"(d) : "l"(a), "l"(b), "l"(c));
    return d;
}
__device__ __forceinline__ unsigned int smem_u32(const void* p) {
    unsigned int a;
    asm("{ .reg .u64 t; cvta.to.shared.u64 t, %1; cvt.u32.u64 %0, t; }"
        : "=r"(a) : "l"(p));
    return a;
}

// Pre-pass (unchanged from R12): per node per half; W1 staged in shared.
__global__ __launch_bounds__(256)
void node_gemm_kernel(const float4* __restrict__ x4,
                      const float* __restrict__ W1g,
                      const float* __restrict__ b1g,
                      const long long* __restrict__ ei,
                      float* __restrict__ out) {
    __shared__ __align__(16) float sW1[DF * HID];   // 8 KB
    int half = blockIdx.y;

    for (int i = threadIdx.x; i < DF * HID / 4; i += blockDim.x)
        ((float4*)sW1)[i] = ((const float4*)W1g)[half * (DF * HID / 4) + i];
    __syncthreads();

    int node = blockIdx.x * blockDim.x + threadIdx.x;
    if (half == 0 && node < NN) out[node] = 0.0f;
    if (half == 0 && node == 0) {
        int ok64 = 1;
        for (int k = 0; k < 8; k++) {
            long long v = ei[k];
            if (v < 0 || v >= NN) ok64 = 0;
        }
        g_idx_is64 = ok64;
    }
    if (node >= NN) return;

    unsigned long long acc[16];
    if (half == 0) {
        const float2* b1p = (const float2*)b1g;
        #pragma unroll
        for (int j = 0; j < 16; j++) {
            float2 b = __ldg(b1p + j);
            acc[j] = pk2(b.x, b.y);
        }
    } else {
        #pragma unroll
        for (int j = 0; j < 16; j++) acc[j] = 0ULL;
    }

    const float4* xp = x4 + (long)node * (DF / 4);
    #pragma unroll 4
    for (int q = 0; q < DF / 4; q++) {
        float4 xv = __ldg(xp + q);
        float vals[4] = {xv.x, xv.y, xv.z, xv.w};
        #pragma unroll
        for (int c = 0; c < 4; c++) {
            int k = q * 4 + c;
            unsigned long long xx = pk2(vals[c], vals[c]);
            const ulonglong2* wrow = (const ulonglong2*)(sW1 + k * 32);
            #pragma unroll
            for (int m = 0; m < 8; m++) {
                ulonglong2 wv = wrow[m];
                acc[2 * m]     = fma2(xx, wv.x, acc[2 * m]);
                acc[2 * m + 1] = fma2(xx, wv.y, acc[2 * m + 1]);
            }
        }
    }

    __half2 hv[16];
    #pragma unroll
    for (int j = 0; j < 16; j++) {
        float a, b;
        upk2(acc[j], a, b);
        hv[j] = __floats2half2_rn(a, b);
    }
    uint4* dst = (uint4*)((char*)g_ABh + (long)node * 128 + half * 64);
    const uint4* src = (const uint4*)hv;
    #pragma unroll
    for (int m = 0; m < 4; m++) dst[m] = src[m];
}

// Layer-2 + layer-3 for one edge pair; hh arrays in fp16, W2 from constant,
// b2/W3 warp-uniform global reads.
__device__ __forceinline__ void pair_tail(const __half2* hhA, const __half2* hhB,
                                          const float* __restrict__ b2g,
                                          const float* __restrict__ W3g,
                                          float b3v, float& wA, float& wB) {
    unsigned long long gA[16], gB[16];
    const float2* b2p = (const float2*)b2g;
    #pragma unroll
    for (int j = 0; j < 16; j++) {
        float2 b = __ldg(b2p + j);
        unsigned long long bb = pk2(b.x, b.y);
        gA[j] = bb; gB[j] = bb;
    }

    #pragma unroll 2
    for (int kk = 0; kk < 16; kk++) {
        float2 fA = __half22float2(hhA[kk]);
        float2 fB = __half22float2(hhB[kk]);
        {
            unsigned long long xA = pk2(fA.x, fA.x);
            unsigned long long xB = pk2(fB.x, fB.x);
            const ulonglong2* wr = (const ulonglong2*)(cW2 + (2 * kk) * 32);
            #pragma unroll
            for (int m = 0; m < 8; m++) {
                ulonglong2 wv = wr[m];                // LDC.128 shared by pair
                gA[2 * m]     = fma2(xA, wv.x, gA[2 * m]);
                gA[2 * m + 1] = fma2(xA, wv.y, gA[2 * m + 1]);
                gB[2 * m]     = fma2(xB, wv.x, gB[2 * m]);
                gB[2 * m + 1] = fma2(xB, wv.y, gB[2 * m + 1]);
            }
        }
        {
            unsigned long long xA = pk2(fA.y, fA.y);
            unsigned long long xB = pk2(fB.y, fB.y);
            const ulonglong2* wr = (const ulonglong2*)(cW2 + (2 * kk + 1) * 32);
            #pragma unroll
            for (int m = 0; m < 8; m++) {
                ulonglong2 wv = wr[m];
                gA[2 * m]     = fma2(xA, wv.x, gA[2 * m]);
                gA[2 * m + 1] = fma2(xA, wv.y, gA[2 * m + 1]);
                gB[2 * m]     = fma2(xB, wv.x, gB[2 * m]);
                gB[2 * m + 1] = fma2(xB, wv.y, gB[2 * m + 1]);
            }
        }
    }

    wA = b3v; wB = b3v;
    #pragma unroll
    for (int j = 0; j < 16; j++) {
        float a, b;
        float2 w3 = __ldg((const float2*)W3g + j);
        upk2(gA[j], a, b);
        wA = fmaf(fmaxf(a, 0.0f), w3.x, wA);
        wA = fmaf(fmaxf(b, 0.0f), w3.y, wA);
        upk2(gB[j], a, b);
        wB = fmaf(fmaxf(a, 0.0f), w3.x, wB);
        wB = fmaf(fmaxf(b, 0.0f), w3.y, wB);
    }
}

// Edge kernel: 4 edges (2 pairs) per thread. Pair 0 gathers via LDG (regs);
// pair 1 gathers via cp.async into a 256B/thread smem slot, fully hidden
// behind pair 0's layer-2/3 compute.
__global__ __launch_bounds__(128, 4)
void edge_mlp_kernel(const void* __restrict__ ei_raw,
                     const float* __restrict__ u,
                     const float* __restrict__ b2g,
                     const float* __restrict__ W3g,
                     const float* __restrict__ b3g,
                     float* __restrict__ out)
{
    __shared__ __align__(16) char sbuf[128 * 256];   // 32 KB

    long e = ((long)blockIdx.x * 128 + threadIdx.x) * 4;
    if (e >= NE) return;   // NE % 4 == 0, so whole quad is valid when e < NE

    int r[4], c[4];
    if (g_idx_is64) {
        const long long* eib = (const long long*)ei_raw;
        longlong2 r01 = __ldg((const longlong2*)(eib + e));
        longlong2 r23 = __ldg((const longlong2*)(eib + e) + 1);
        longlong2 c01 = __ldg((const longlong2*)(eib + NE + e));
        longlong2 c23 = __ldg((const longlong2*)(eib + NE + e) + 1);
        r[0] = (int)r01.x; r[1] = (int)r01.y; r[2] = (int)r23.x; r[3] = (int)r23.y;
        c[0] = (int)c01.x; c[1] = (int)c01.y; c[2] = (int)c23.x; c[3] = (int)c23.y;
    } else {
        const int* eib = (const int*)ei_raw;
        int4 rr = __ldg((const int4*)(eib + e));
        int4 cc = __ldg((const int4*)(eib + NE + e));
        r[0] = rr.x; r[1] = rr.y; r[2] = rr.z; r[3] = rr.w;
        c[0] = cc.x; c[1] = cc.y; c[2] = cc.z; c[3] = cc.w;
    }
    #pragma unroll
    for (int i = 0; i < 4; i++) {
        r[i] = min(max(r[i], 0), NN - 1);
        c[i] = min(max(c[i], 0), NN - 1);
    }

    float uc[4];
    #pragma unroll
    for (int i = 0; i < 4; i++) uc[i] = __ldg(u + c[i]);

    const char* ab = (const char*)g_ABh;

    // ---- pair 0: gather via LDG (front-batched) ----
    const uint4* ap0 = (const uint4*)(ab + (long)r[0] * 128);
    const uint4* bp0 = (const uint4*)(ab + (long)c[0] * 128 + 64);
    const uint4* ap1 = (const uint4*)(ab + (long)r[1] * 128);
    const uint4* bp1 = (const uint4*)(ab + (long)c[1] * 128 + 64);
    uint4 raw[16];
    #pragma unroll
    for (int m = 0; m < 4; m++) {
        raw[m]      = __ldg(ap0 + m);
        raw[4 + m]  = __ldg(bp0 + m);
        raw[8 + m]  = __ldg(ap1 + m);
        raw[12 + m] = __ldg(bp1 + m);
    }

    // ---- pair 1: gather via cp.async into own smem slot (swizzled) ----
    char* slot = sbuf + threadIdx.x * 256;
    unsigned int sw = threadIdx.x & 15;
    unsigned int sbase = smem_u32(slot);
    #pragma unroll
    for (int h = 0; h < 4; h++) {
        long node = (h == 0) ? r[2] : (h == 1) ? c[2] : (h == 2) ? r[3] : c[3];
        const char* src = ab + node * 128 + ((h & 1) ? 64 : 0);
        #pragma unroll
        for (int m = 0; m < 4; m++) {
            unsigned int d = sbase + (((unsigned)(h * 4 + m) ^ sw) << 4);
            asm volatile("cp.async.cg.shared.global [%0], [%1], 16;"
                         :: "r"(d), "l"(src + m * 16) : "memory");
        }
    }
    asm volatile("cp.async.commit_group;" ::: "memory");

    // fold pair 0 -> fp16 activations
    __half2 hh0[16], hh1[16];
    const __half2 z2 = __half2half2(__ushort_as_half(0));
    #pragma unroll
    for (int m = 0; m < 4; m++) {
        const __half2* a0 = (const __half2*)&raw[m];
        const __half2* b0 = (const __half2*)&raw[4 + m];
        const __half2* a1 = (const __half2*)&raw[8 + m];
        const __half2* b1v = (const __half2*)&raw[12 + m];
        #pragma unroll
        for (int p = 0; p < 4; p++) {
            hh0[m * 4 + p] = __hmax2(__hadd2(a0[p], b0[p]), z2);
            hh1[m * 4 + p] = __hmax2(__hadd2(a1[p], b1v[p]), z2);
        }
    }

    float b3v = __ldg(b3g);

    // layer 2/3 + scatter for pair 0 (covers pair 1's cp.async latency)
    {
        float w0, w1;
        pair_tail(hh0, hh1, b2g, W3g, b3v, w0, w1);
        atomicAdd(out + r[0], w0 * uc[0]);
        atomicAdd(out + r[1], w1 * uc[1]);
    }

    // ---- pair 1: fold from smem, then layer 2/3 + scatter ----
    asm volatile("cp.async.wait_group 0;" ::: "memory");

    __half2 hh2[16], hh3[16];
    #pragma unroll
    for (int m = 0; m < 4; m++) {
        uint4 a2 = *(const uint4*)(slot + (((unsigned)(m) ^ sw) << 4));
        uint4 b2 = *(const uint4*)(slot + (((unsigned)(4 + m) ^ sw) << 4));
        uint4 a3 = *(const uint4*)(slot + (((unsigned)(8 + m) ^ sw) << 4));
        uint4 b3q = *(const uint4*)(slot + (((unsigned)(12 + m) ^ sw) << 4));
        const __half2* ha2 = (const __half2*)&a2;
        const __half2* hb2 = (const __half2*)&b2;
        const __half2* ha3 = (const __half2*)&a3;
        const __half2* hb3 = (const __half2*)&b3q;
        #pragma unroll
        for (int p = 0; p < 4; p++) {
            hh2[m * 4 + p] = __hmax2(__hadd2(ha2[p], hb2[p]), z2);
            hh3[m * 4 + p] = __hmax2(__hadd2(ha3[p], hb3[p]), z2);
        }
    }
    {
        float w2, w3;
        pair_tail(hh2, hh3, b2g, W3g, b3v, w2, w3);
        atomicAdd(out + r[2], w2 * uc[2]);
        atomicAdd(out + r[3], w3 * uc[3]);
    }
}

extern "C" void kernel_launch(void* const* d_in, const int* in_sizes, int n_in,
                              void* d_out, int out_size) {
    const float* x  = (const float*)d_in[0];
    const void*  ei = d_in[1];
    const float* u  = (const float*)d_in[2];
    const float* W1 = (const float*)d_in[3];
    const float* b1 = (const float*)d_in[4];
    const float* W2 = (const float*)d_in[5];
    const float* b2 = (const float*)d_in[6];
    const float* W3 = (const float*)d_in[7];
    const float* b3 = (const float*)d_in[8];
    float* out = (float*)d_out;

    cudaMemcpyToSymbolAsync(cW2, W2, HID * HID * sizeof(float), 0,
                            cudaMemcpyDeviceToDevice, 0);

    dim3 gg((NN + 255) / 256, 2);
    node_gemm_kernel<<<gg, 256>>>((const float4*)x, W1, b1,
                                  (const long long*)ei, out);

    int quads = NE / 4;                       // 300000
    edge_mlp_kernel<<<(quads + 127) / 128, 128>>>(ei, u, b2, W3, b3, out);
}